// round 17
// baseline (speedup 1.0000x reference)
#include <cuda_runtime.h>

// segmentation (2,1,256,256,256) float32, values exactly 0.0f / 1.0f
#define DIM    256
#define NBAT   2
#define TLX    64            // tile width  (x, contiguous)
#define TLY    32            // tile height (y)
#define CZ     64            // z-chunk per block
#define NCHUNK (DIM / CZ)    // 4
#define M4     0x0F0F0F0Fu

// pack 4 floats (exactly 0.0f/1.0f) into 4 bytes of a u32 (0x00/0x01)
__device__ __forceinline__ unsigned pack01(float4 v) {
    unsigned q0 = __byte_perm(__float_as_uint(v.x), __float_as_uint(v.y), 0x0073);
    unsigned q1 = __byte_perm(__float_as_uint(v.z), __float_as_uint(v.w), 0x7300);
    return (q0 | q1) & 0x01010101u;
}

// x 5-tap [1,2,3,2,1] on packed bytes; A,B,C consecutive u32s
__device__ __forceinline__ unsigned xconv(unsigned A, unsigned B, unsigned C) {
    const unsigned s2 = __byte_perm(A, B, 0x5432);
    const unsigned s3 = __byte_perm(A, B, 0x6543);
    const unsigned s5 = __byte_perm(B, C, 0x4321);
    const unsigned s6 = __byte_perm(B, C, 0x5432);
    return (s2 + s6) + 2u * (s3 + s5) + 3u * B;      // bytes <= 9
}

// per-byte min(v,9); input bytes <= 81
__device__ __forceinline__ unsigned clamp9(unsigned o) {
    const unsigned flag = (o + 0x76767676u) & 0x80808080u;
    const unsigned full = (flag - (flag >> 7)) | flag;
    return (o & ~full) | (0x09090909u & full);
}

// expand flag byte k (bit 7) of m into 0.0f / 1.0f  (proven shift form)
__device__ __forceinline__ float flag2f(unsigned m, int k) {
    return __uint_as_float((unsigned)(((int)(m << (24 - 8 * k))) >> 31) & 0x3F800000u);
}

__global__ __launch_bounds__(512, 2)
void skel_kernel(const float* __restrict__ in, float* __restrict__ out) {
    // 6-slot z-ring of raw halo planes (u8): 36 rows x 72 bytes
    __shared__ __align__(16) unsigned char raw[6][36 * 72];   // 15.2 KB
    // double-buffered pair of x-conv planes, flat [row*16+vec], 576 u32 each
    __shared__ __align__(16) unsigned xcf[2][2][576];         // 9.2 KB

    const int t  = threadIdx.x;              // 0..511
    const int x0 = blockIdx.x * TLX;
    const int y0 = blockIdx.y * TLY;
    const int b  = blockIdx.z / NCHUNK;
    const int zs = (blockIdx.z % NCHUNK) * CZ;

    const size_t planeSz = (size_t)DIM * DIM;
    const float* inb  = in  + (size_t)b * DIM * planeSz;
    float*       outb = out + (size_t)b * DIM * planeSz;

    // ---- halo-load descriptors: 648 float4 tasks = 36 rows x 18 vec ----
    int h1_soff, h1_src; bool h1_ok;
    {
        const int r = t / 18, v = t - 18 * r;
        const int gy = y0 - 2 + r, gx = x0 - 4 + 4 * v;
        h1_ok  = ((unsigned)gy < DIM) && ((unsigned)gx < DIM);
        h1_src = gy * DIM + gx;
        h1_soff = 72 * r + 4 * v;
    }
    const bool h2a = (t < 136);
    int h2_soff = 0, h2_src = 0; bool h2_ok = false;
    if (h2a) {
        const int i = t + 512;
        const int r = i / 18, v = i - 18 * r;
        const int gy = y0 - 2 + r, gx = x0 - 4 + 4 * v;
        h2_ok  = ((unsigned)gy < DIM) && ((unsigned)gx < DIM);
        h2_src = gy * DIM + gx;
        h2_soff = 72 * r + 4 * v;
    }

    // ---- x-conv tasks: 576/plane; extras: plane A on t>=448, plane B on t<64 ----
    const int  x1_ro = 72 * (t >> 4) + 4 * (t & 15);              // raw byte offset
    const bool xA2   = (t >= 448);
    const int  x2a_ro = 72 * ((t + 64) >> 4) + 4 * ((t + 64) & 15);
    const bool xB2   = (t < 64);
    const int  x2b_ro = 72 * ((t + 512) >> 4) + 4 * ((t + 512) & 15);

    // ---- output mapping: flat xc index of row (orow+k) is t + 16k ----
    const int orow = t >> 4, ocol = (t & 15) * 4;
    const long long obase = (long long)(y0 + orow) * DIM + (x0 + ocol);

    // register ring: clamped xy-conv bytes (<=9) | center bit 4; z window of 5
    unsigned r0 = 0, r1 = 0, r2 = 0, r3 = 0, r4 = 0;

    // ---- preload planes gz=zs-2 -> slot 0, gz=zs-1 -> slot 1 ----
    {
        const bool zok = (zs > 0);
        float4 v0 = make_float4(0.f,0.f,0.f,0.f), v1 = v0, w0 = v0, w1 = v0;
        const float* pl0 = inb + (size_t)(zs - 2) * planeSz;
        const float* pl1 = pl0 + planeSz;
        if (zok && h1_ok) { v0 = *(const float4*)(pl0 + h1_src);
                            v1 = *(const float4*)(pl1 + h1_src); }
        *(unsigned*)(raw[0] + h1_soff) = pack01(v0);
        *(unsigned*)(raw[1] + h1_soff) = pack01(v1);
        if (h2a) {
            if (zok && h2_ok) { w0 = *(const float4*)(pl0 + h2_src);
                                w1 = *(const float4*)(pl1 + h2_src); }
            *(unsigned*)(raw[0] + h2_soff) = pack01(w0);
            *(unsigned*)(raw[1] + h2_soff) = pack01(w1);
        }
    }
    __syncthreads();

#pragma unroll 2
    for (int it = 0; it < 34; ++it) {
        const int sA = (2 * it) % 6;            // plane zi=2it
        const int sB = (2 * it + 1) % 6;        // plane zi=2it+1
        const int sC = (2 * it + 2) % 6;        // commit target A
        const int sD = (2 * it + 3) % 6;        // commit target B
        unsigned* xcA = xcf[it & 1][0];
        unsigned* xcB = xcf[it & 1][1];

        // ---- prefetch planes gz = zs+2it, zs+2it+1 ----
        float4 pa1 = make_float4(0.f,0.f,0.f,0.f), pa2 = pa1, pb1 = pa1, pb2 = pa1;
        {
            const int gzA = zs + 2 * it;
            const bool okA = (it < 33) && (gzA < DIM);
            const bool okB = (it < 33) && (gzA + 1 < DIM);
            const float* plA = inb + (size_t)gzA * planeSz;
            const float* plB = plA + planeSz;
            if (okA && h1_ok) pa1 = *(const float4*)(plA + h1_src);
            if (okB && h1_ok) pb1 = *(const float4*)(plB + h1_src);
            if (h2a) {
                if (okA && h2_ok) pa2 = *(const float4*)(plA + h2_src);
                if (okB && h2_ok) pb2 = *(const float4*)(plB + h2_src);
            }
        }

        // ---- x-conv both planes, center bit embedded at bit 4 ----
        {
            const unsigned char* rr = &raw[sA][x1_ro];
            const unsigned B1 = *(const unsigned*)(rr + 4);
            xcA[t] = xconv(*(const unsigned*)rr, B1, *(const unsigned*)(rr + 8))
                   | (B1 << 4);
            const unsigned char* rs = &raw[sB][x1_ro];
            const unsigned B2 = *(const unsigned*)(rs + 4);
            xcB[t] = xconv(*(const unsigned*)rs, B2, *(const unsigned*)(rs + 8))
                   | (B2 << 4);
            if (xA2) {
                const unsigned char* rt = &raw[sA][x2a_ro];
                const unsigned B3 = *(const unsigned*)(rt + 4);
                xcA[t + 64] = xconv(*(const unsigned*)rt, B3, *(const unsigned*)(rt + 8))
                            | (B3 << 4);
            }
            if (xB2) {
                const unsigned char* ru = &raw[sB][x2b_ro];
                const unsigned B4 = *(const unsigned*)(ru + 4);
                xcB[t + 512] = xconv(*(const unsigned*)ru, B4, *(const unsigned*)(ru + 8))
                             | (B4 << 4);
            }
        }

        // ---- commit prefetched planes into slots sC, sD (pre-barrier) ----
        *(unsigned*)(raw[sC] + h1_soff) = pack01(pa1);
        *(unsigned*)(raw[sD] + h1_soff) = pack01(pb1);
        if (h2a) {
            *(unsigned*)(raw[sC] + h2_soff) = pack01(pa2);
            *(unsigned*)(raw[sD] + h2_soff) = pack01(pb2);
        }
        __syncthreads();   // xc ready AND raw[sC/sD] ready (single barrier)

        // ---- plane A: y-conv + clamp + center carry, ring push, emit ----
        {
            const unsigned a0 = xcA[t];
            const unsigned a1 = xcA[t + 16];
            const unsigned a2 = xcA[t + 32];
            const unsigned a3 = xcA[t + 48];
            const unsigned a4 = xcA[t + 64];
            const unsigned p  = clamp9(((a0 & M4) + (a4 & M4))
                                       + 2u * ((a1 & M4) + (a3 & M4))
                                       + 3u * (a2 & M4)) | (a2 & 0x10101010u);
            r0 = r1; r1 = r2; r2 = r3; r3 = r4; r4 = p;
        }
        if (it >= 2) {
            const unsigned d = ((r0 & M4) + (r4 & M4))
                             + 2u * ((r1 & M4) + (r3 & M4)) + 3u * (r2 & M4);
            const unsigned m = (d + 0x77777777u) & ~(r2 << 3) & 0x80808080u;
            float4 o = make_float4(flag2f(m, 0), flag2f(m, 1), flag2f(m, 2), flag2f(m, 3));
            __stcs((float4*)(outb + (size_t)(zs + 2 * it - 4) * planeSz + obase), o);
        }

        // ---- plane B ----
        {
            const unsigned a0 = xcB[t];
            const unsigned a1 = xcB[t + 16];
            const unsigned a2 = xcB[t + 32];
            const unsigned a3 = xcB[t + 48];
            const unsigned a4 = xcB[t + 64];
            const unsigned p  = clamp9(((a0 & M4) + (a4 & M4))
                                       + 2u * ((a1 & M4) + (a3 & M4))
                                       + 3u * (a2 & M4)) | (a2 & 0x10101010u);
            r0 = r1; r1 = r2; r2 = r3; r3 = r4; r4 = p;
        }
        if (it >= 2) {
            const unsigned d = ((r0 & M4) + (r4 & M4))
                             + 2u * ((r1 & M4) + (r3 & M4)) + 3u * (r2 & M4);
            const unsigned m = (d + 0x77777777u) & ~(r2 << 3) & 0x80808080u;
            float4 o = make_float4(flag2f(m, 0), flag2f(m, 1), flag2f(m, 2), flag2f(m, 3));
            __stcs((float4*)(outb + (size_t)(zs + 2 * it - 3) * planeSz + obase), o);
        }
    }
}

extern "C" void kernel_launch(void* const* d_in, const int* in_sizes, int n_in,
                              void* d_out, int out_size) {
    (void)in_sizes; (void)n_in; (void)out_size;
    const float* seg = (const float*)d_in[0];
    float* out = (float*)d_out;

    dim3 block(512, 1, 1);
    dim3 grid(DIM / TLX, DIM / TLY, NBAT * NCHUNK);   // 4 x 8 x 8 = 256 blocks
    skel_kernel<<<grid, block>>>(seg, out);
}